// round 1
// baseline (speedup 1.0000x reference)
#include <cuda_runtime.h>

#define NGRAPH 256
#define M      512
#define KNN    6
#define C      32
#define NWARP  16          // 512 threads
#define FINF   3.402823466e38f

struct SmemLayout {
    float4 pos4[M];        // x, y, z, |p|^2          8 KB
    float  xs[M];          //                          2 KB
    int    idx[M * KNN];   //                         12 KB
    float  H[M * C];       //                         64 KB
    float  U[M * C];       //                         64 KB
    float  red[NWARP * C]; //                          2 KB
};                         // total 155648 B

__global__ void __launch_bounds__(512, 1) gcn_fused_kernel(
    const float* __restrict__ x,   const float* __restrict__ pos,
    const float* __restrict__ W1a, const float* __restrict__ b1a,
    const float* __restrict__ W2a, const float* __restrict__ b2a,
    const float* __restrict__ W1b, const float* __restrict__ b1b,
    const float* __restrict__ W2b, const float* __restrict__ b2b,
    const float* __restrict__ W1c, const float* __restrict__ b1c,
    const float* __restrict__ W2c, const float* __restrict__ b2c,
    const float* __restrict__ Wr,  const float* __restrict__ brr,
    float* __restrict__ out)
{
    extern __shared__ char smem_raw[];
    SmemLayout& sm = *reinterpret_cast<SmemLayout*>(smem_raw);

    const int b    = blockIdx.x;
    const int tid  = threadIdx.x;
    const int lane = tid & 31;
    const int wid  = tid >> 5;

    // ---- stage pos (+ squared norm) and x ----
    {
        const int n = tid;
        const float* p = pos + ((size_t)b * M + n) * 3;
        float px = p[0], py = p[1], pz = p[2];
        float s = px * px + py * py + pz * pz;
        sm.pos4[n] = make_float4(px, py, pz, s);
        sm.xs[n]   = x[(size_t)b * M + n];
    }
    __syncthreads();

    // ---- brute-force KNN: one thread per row, register top-6 (stable) ----
    {
        const int n = tid;
        float4 pn = sm.pos4[n];
        float bd[KNN];
        int   bi[KNN];
#pragma unroll
        for (int k = 0; k < KNN; k++) { bd[k] = FINF; bi[k] = 0; }
        for (int j = 0; j < M; j++) {
            float4 pj = sm.pos4[j];
            // exact reference formula: sq_i + sq_j - 2*dot
            float d2 = pn.w + pj.w
                     - 2.0f * (pn.x * pj.x + pn.y * pj.y + pn.z * pj.z);
            if (d2 < bd[KNN - 1]) {           // strict: ties keep earlier j
                bd[KNN - 1] = d2; bi[KNN - 1] = j;
#pragma unroll
                for (int k = KNN - 1; k > 0; k--) {
                    if (bd[k] < bd[k - 1]) {  // strict: stable insertion
                        float td = bd[k]; bd[k] = bd[k - 1]; bd[k - 1] = td;
                        int   ti = bi[k]; bi[k] = bi[k - 1]; bi[k - 1] = ti;
                    }
                }
            }
        }
#pragma unroll
        for (int k = 0; k < KNN; k++) sm.idx[n * KNN + k] = bi[k];
    }
    __syncthreads();

    // ============ layer A (Cin=4, per-node MLP -> U, no shfl for layer1) ============
    {
        float w10 = W1a[lane * 4 + 0], w11 = W1a[lane * 4 + 1];
        float w12 = W1a[lane * 4 + 2], w13 = W1a[lane * 4 + 3];
        float bb1 = b1a[lane], bb2 = b2a[lane];
        float w2r[C];
#pragma unroll
        for (int c = 0; c < C; c++) w2r[c] = W2a[lane * C + c];

        for (int n = wid; n < M; n += NWARP) {
            float4 p = sm.pos4[n];
            float xv = sm.xs[n];
            float a = fmaf(w10, xv, fmaf(w11, p.x, fmaf(w12, p.y, fmaf(w13, p.z, bb1))));
            a = fmaxf(a, 0.0f);
            float u = bb2;
#pragma unroll
            for (int c = 0; c < C; c++)
                u = fmaf(w2r[c], __shfl_sync(0xffffffffu, a, c), u);
            sm.U[n * C + lane] = u;
        }
    }
    __syncthreads();
    // gather-max -> H
    for (int n = wid; n < M; n += NWARP) {
        float m = -FINF;
#pragma unroll
        for (int k = 0; k < KNN; k++)
            m = fmaxf(m, sm.U[sm.idx[n * KNN + k] * C + lane]);
        sm.H[n * C + lane] = fmaxf(m, 0.0f);
    }
    __syncthreads();

    // ============ layers B, C (Cin=32) ============
    auto layer32 = [&](const float* W1, const float* B1,
                       const float* W2, const float* B2) {
        float w1r[C], w2r[C];
#pragma unroll
        for (int c = 0; c < C; c++) {
            w1r[c] = W1[lane * C + c];
            w2r[c] = W2[lane * C + c];
        }
        float bb1 = B1[lane], bb2 = B2[lane];

        for (int n = wid; n < M; n += NWARP) {
            const float* hrow = &sm.H[n * C];
            float a = bb1;
#pragma unroll
            for (int c = 0; c < C; c++)            // SMEM broadcast reads
                a = fmaf(w1r[c], hrow[c], a);
            a = fmaxf(a, 0.0f);
            float u = bb2;
#pragma unroll
            for (int c = 0; c < C; c++)
                u = fmaf(w2r[c], __shfl_sync(0xffffffffu, a, c), u);
            sm.U[n * C + lane] = u;
        }
        __syncthreads();
        for (int n = wid; n < M; n += NWARP) {
            float m = -FINF;
#pragma unroll
            for (int k = 0; k < KNN; k++)
                m = fmaxf(m, sm.U[sm.idx[n * KNN + k] * C + lane]);
            sm.H[n * C + lane] = fmaxf(m, 0.0f);
        }
        __syncthreads();
    };
    layer32(W1b, b1b, W2b, b2b);
    layer32(W1c, b1c, W2c, b2c);

    // ============ global max pool + final linear ============
    float g = -FINF;
    for (int n = wid; n < M; n += NWARP)
        g = fmaxf(g, sm.H[n * C + lane]);
    sm.red[wid * C + lane] = g;
    __syncthreads();

    if (wid == 0) {
        float gg = sm.red[lane];
#pragma unroll
        for (int w = 1; w < NWARP; w++)
            gg = fmaxf(gg, sm.red[w * C + lane]);
#pragma unroll
        for (int od = 0; od < 6; od++) {
            float p = Wr[od * C + lane] * gg;
#pragma unroll
            for (int off = 16; off > 0; off >>= 1)
                p += __shfl_xor_sync(0xffffffffu, p, off);
            if (lane == 0) out[b * 6 + od] = p + brr[od];
        }
    }
}

extern "C" void kernel_launch(void* const* d_in, const int* in_sizes, int n_in,
                              void* d_out, int out_size)
{
    const float* x   = (const float*)d_in[0];
    const float* pos = (const float*)d_in[1];
    // d_in[2] = batch (int64), unused (implicit in layout)
    const float* W1a = (const float*)d_in[3];
    const float* b1a = (const float*)d_in[4];
    const float* W2a = (const float*)d_in[5];
    const float* b2a = (const float*)d_in[6];
    const float* W1b = (const float*)d_in[7];
    const float* b1b = (const float*)d_in[8];
    const float* W2b = (const float*)d_in[9];
    const float* b2b = (const float*)d_in[10];
    const float* W1c = (const float*)d_in[11];
    const float* b1c = (const float*)d_in[12];
    const float* W2c = (const float*)d_in[13];
    const float* b2c = (const float*)d_in[14];
    const float* Wr  = (const float*)d_in[15];
    const float* brr = (const float*)d_in[16];
    float* out = (float*)d_out;

    const size_t smem = sizeof(SmemLayout);
    cudaFuncSetAttribute(gcn_fused_kernel,
                         cudaFuncAttributeMaxDynamicSharedMemorySize, (int)smem);

    gcn_fused_kernel<<<NGRAPH, 512, smem>>>(
        x, pos,
        W1a, b1a, W2a, b2a,
        W1b, b1b, W2b, b2b,
        W1c, b1c, W2c, b2c,
        Wr, brr, out);
}

// round 2
// speedup vs baseline: 1.1197x; 1.1197x over previous
#include <cuda_runtime.h>

#define NGRAPH 256
#define M      512
#define KNN    6
#define C      32
#define NWARP  16          // 512 threads
#define FINF   3.402823466e38f

struct SmemLayout {
    float4 pos4[M];          //   8 KB  x,y,z,|p|^2
    float  xs[M];            //   2 KB
    int    idx[M * 8];       //  16 KB  (6 used, padded to 8 for int4/int2 loads)
    float  U[2][M * C];      // 128 KB  ping-pong node-major [n][c]
    float  hb[NWARP][2][C];  //   4 KB  per-warp h staging (2 nodes)
    float  ab[NWARP][2][C];  //   4 KB  per-warp a staging (2 nodes)
    float  red[NWARP * C];   //   2 KB
};                           // 164 KB total

__device__ __forceinline__ void kins(float (&bd)[KNN], int (&bi)[KNN],
                                     float xd, int xi)
{
#pragma unroll
    for (int k = 0; k < KNN; k++) {
        bool  p  = xd < bd[k];          // strict: stable (ties keep earlier j)
        float td = bd[k];
        int   ti = bi[k];
        bd[k] = p ? xd : bd[k];
        bi[k] = p ? xi : bi[k];
        xd    = p ? td : xd;
        xi    = p ? ti : xi;
    }
}

__global__ void __launch_bounds__(512, 1) gcn_fused_kernel(
    const float* __restrict__ x,   const float* __restrict__ pos,
    const float* __restrict__ W1a, const float* __restrict__ b1a,
    const float* __restrict__ W2a, const float* __restrict__ b2a,
    const float* __restrict__ W1b, const float* __restrict__ b1b,
    const float* __restrict__ W2b, const float* __restrict__ b2b,
    const float* __restrict__ W1c, const float* __restrict__ b1c,
    const float* __restrict__ W2c, const float* __restrict__ b2c,
    const float* __restrict__ Wr,  const float* __restrict__ brr,
    float* __restrict__ out)
{
    extern __shared__ char smem_raw[];
    SmemLayout& sm = *reinterpret_cast<SmemLayout*>(smem_raw);

    const int b    = blockIdx.x;
    const int tid  = threadIdx.x;
    const int lane = tid & 31;
    const int wid  = tid >> 5;

    // ---- stage pos (+ squared norm) and x ----
    {
        const int n = tid;
        const float* p = pos + ((size_t)b * M + n) * 3;
        float px = p[0], py = p[1], pz = p[2];
        float s = px * px + py * py + pz * pz;
        sm.pos4[n] = make_float4(px, py, pz, s);
        sm.xs[n]   = x[(size_t)b * M + n];
    }
    __syncthreads();

    // ---- brute-force KNN: thread-per-row, predicated top-6 insert ----
    {
        const int n = tid;
        float4 pn = sm.pos4[n];
        float bd[KNN];
        int   bi[KNN];
#pragma unroll
        for (int k = 0; k < KNN; k++) { bd[k] = FINF; bi[k] = 0; }
#pragma unroll 2
        for (int j = 0; j < M; j += 2) {
            float4 pa = sm.pos4[j];
            float4 pb = sm.pos4[j + 1];
            float dota = fmaf(pn.x, pa.x, fmaf(pn.y, pa.y, pn.z * pa.z));
            float dotb = fmaf(pn.x, pb.x, fmaf(pn.y, pb.y, pn.z * pb.z));
            float d2a  = fmaf(-2.0f, dota, pn.w + pa.w);
            float d2b  = fmaf(-2.0f, dotb, pn.w + pb.w);
            if (d2a < bd[KNN - 1]) kins(bd, bi, d2a, j);
            if (d2b < bd[KNN - 1]) kins(bd, bi, d2b, j + 1);
        }
#pragma unroll
        for (int k = 0; k < KNN; k++) sm.idx[n * 8 + k] = bi[k];
    }
    __syncthreads();

    float* hb0 = &sm.hb[wid][0][0];
    float* hb1 = &sm.hb[wid][1][0];
    float* ab0 = &sm.ab[wid][0][0];
    float* ab1 = &sm.ab[wid][1][0];
    const int base = wid * 32;

    // ============ layer A: Cin=4 MLP per node -> U[0] ============
    {
        float w10 = W1a[lane * 4 + 0], w11 = W1a[lane * 4 + 1];
        float w12 = W1a[lane * 4 + 2], w13 = W1a[lane * 4 + 3];
        float bb1 = b1a[lane], bb2 = b2a[lane];
        float w2r[C];
#pragma unroll
        for (int c = 0; c < C; c++) w2r[c] = W2a[lane * C + c];
        float* dst = &sm.U[0][0];

#pragma unroll 1
        for (int t = 0; t < 16; t++) {
            int n0 = base + 2 * t, n1 = n0 + 1;
            float4 p0 = sm.pos4[n0]; float x0 = sm.xs[n0];
            float4 p1 = sm.pos4[n1]; float x1 = sm.xs[n1];
            float a0 = fmaf(w10, x0, fmaf(w11, p0.x, fmaf(w12, p0.y, fmaf(w13, p0.z, bb1))));
            float a1 = fmaf(w10, x1, fmaf(w11, p1.x, fmaf(w12, p1.y, fmaf(w13, p1.z, bb1))));
            ab0[lane] = fmaxf(a0, 0.0f);
            ab1[lane] = fmaxf(a1, 0.0f);
            __syncwarp();
            const float4* a40 = (const float4*)ab0;
            const float4* a41 = (const float4*)ab1;
            float u00 = bb2, u01 = 0.f, u02 = 0.f, u03 = 0.f;
            float u10 = bb2, u11 = 0.f, u12 = 0.f, u13 = 0.f;
#pragma unroll
            for (int q = 0; q < 8; q++) {
                float4 v0 = a40[q], v1 = a41[q];
                u00 = fmaf(w2r[4*q+0], v0.x, u00); u01 = fmaf(w2r[4*q+1], v0.y, u01);
                u02 = fmaf(w2r[4*q+2], v0.z, u02); u03 = fmaf(w2r[4*q+3], v0.w, u03);
                u10 = fmaf(w2r[4*q+0], v1.x, u10); u11 = fmaf(w2r[4*q+1], v1.y, u11);
                u12 = fmaf(w2r[4*q+2], v1.z, u12); u13 = fmaf(w2r[4*q+3], v1.w, u13);
            }
            dst[n0 * C + lane] = (u00 + u01) + (u02 + u03);
            dst[n1 * C + lane] = (u10 + u11) + (u12 + u13);
            __syncwarp();
        }
    }
    __syncthreads();

    // ============ layers B, C: fused gather-max+relu -> 2-layer MLP ============
    auto layer32 = [&](const float* __restrict__ src, float* __restrict__ dst,
                       const float* W1, const float* B1,
                       const float* W2, const float* B2) {
        float w1r[C], w2r[C];
#pragma unroll
        for (int c = 0; c < C; c++) {
            w1r[c] = W1[lane * C + c];
            w2r[c] = W2[lane * C + c];
        }
        float bb1 = B1[lane], bb2 = B2[lane];

#pragma unroll 1
        for (int t = 0; t < 16; t++) {
            int n0 = base + 2 * t, n1 = n0 + 1;
            const int4 ia0 = *(const int4*)&sm.idx[n0 * 8];
            const int2 ib0 = *(const int2*)&sm.idx[n0 * 8 + 4];
            const int4 ia1 = *(const int4*)&sm.idx[n1 * 8];
            const int2 ib1 = *(const int2*)&sm.idx[n1 * 8 + 4];
            float m0 =            src[ia0.x * C + lane];
            m0 = fmaxf(m0, src[ia0.y * C + lane]);
            m0 = fmaxf(m0, src[ia0.z * C + lane]);
            m0 = fmaxf(m0, src[ia0.w * C + lane]);
            m0 = fmaxf(m0, src[ib0.x * C + lane]);
            m0 = fmaxf(m0, src[ib0.y * C + lane]);
            float m1 =            src[ia1.x * C + lane];
            m1 = fmaxf(m1, src[ia1.y * C + lane]);
            m1 = fmaxf(m1, src[ia1.z * C + lane]);
            m1 = fmaxf(m1, src[ia1.w * C + lane]);
            m1 = fmaxf(m1, src[ib1.x * C + lane]);
            m1 = fmaxf(m1, src[ib1.y * C + lane]);
            hb0[lane] = fmaxf(m0, 0.0f);
            hb1[lane] = fmaxf(m1, 0.0f);
            __syncwarp();

            const float4* h40 = (const float4*)hb0;
            const float4* h41 = (const float4*)hb1;
            float a00 = bb1, a01 = 0.f, a02 = 0.f, a03 = 0.f;
            float a10 = bb1, a11 = 0.f, a12 = 0.f, a13 = 0.f;
#pragma unroll
            for (int q = 0; q < 8; q++) {
                float4 v0 = h40[q], v1 = h41[q];
                a00 = fmaf(w1r[4*q+0], v0.x, a00); a01 = fmaf(w1r[4*q+1], v0.y, a01);
                a02 = fmaf(w1r[4*q+2], v0.z, a02); a03 = fmaf(w1r[4*q+3], v0.w, a03);
                a10 = fmaf(w1r[4*q+0], v1.x, a10); a11 = fmaf(w1r[4*q+1], v1.y, a11);
                a12 = fmaf(w1r[4*q+2], v1.z, a12); a13 = fmaf(w1r[4*q+3], v1.w, a13);
            }
            ab0[lane] = fmaxf((a00 + a01) + (a02 + a03), 0.0f);
            ab1[lane] = fmaxf((a10 + a11) + (a12 + a13), 0.0f);
            __syncwarp();

            const float4* a40 = (const float4*)ab0;
            const float4* a41 = (const float4*)ab1;
            float u00 = bb2, u01 = 0.f, u02 = 0.f, u03 = 0.f;
            float u10 = bb2, u11 = 0.f, u12 = 0.f, u13 = 0.f;
#pragma unroll
            for (int q = 0; q < 8; q++) {
                float4 v0 = a40[q], v1 = a41[q];
                u00 = fmaf(w2r[4*q+0], v0.x, u00); u01 = fmaf(w2r[4*q+1], v0.y, u01);
                u02 = fmaf(w2r[4*q+2], v0.z, u02); u03 = fmaf(w2r[4*q+3], v0.w, u03);
                u10 = fmaf(w2r[4*q+0], v1.x, u10); u11 = fmaf(w2r[4*q+1], v1.y, u11);
                u12 = fmaf(w2r[4*q+2], v1.z, u12); u13 = fmaf(w2r[4*q+3], v1.w, u13);
            }
            dst[n0 * C + lane] = (u00 + u01) + (u02 + u03);
            dst[n1 * C + lane] = (u10 + u11) + (u12 + u13);
            __syncwarp();
        }
        __syncthreads();
    };
    layer32(&sm.U[0][0], &sm.U[1][0], W1b, b1b, W2b, b2b);
    layer32(&sm.U[1][0], &sm.U[0][0], W1c, b1c, W2c, b2c);

    // ============ final gather + relu + global max pool ============
    {
        const float* src = &sm.U[0][0];
        float g = -FINF;
#pragma unroll 1
        for (int t = 0; t < 32; t++) {
            int n = base + t;
            const int4 ia = *(const int4*)&sm.idx[n * 8];
            const int2 ib = *(const int2*)&sm.idx[n * 8 + 4];
            float m =            src[ia.x * C + lane];
            m = fmaxf(m, src[ia.y * C + lane]);
            m = fmaxf(m, src[ia.z * C + lane]);
            m = fmaxf(m, src[ia.w * C + lane]);
            m = fmaxf(m, src[ib.x * C + lane]);
            m = fmaxf(m, src[ib.y * C + lane]);
            g = fmaxf(g, fmaxf(m, 0.0f));     // relu then pool
        }
        sm.red[wid * C + lane] = g;
    }
    __syncthreads();

    if (wid == 0) {
        float gg = sm.red[lane];
#pragma unroll
        for (int w = 1; w < NWARP; w++)
            gg = fmaxf(gg, sm.red[w * C + lane]);
#pragma unroll
        for (int od = 0; od < 6; od++) {
            float p = Wr[od * C + lane] * gg;
#pragma unroll
            for (int off = 16; off > 0; off >>= 1)
                p += __shfl_xor_sync(0xffffffffu, p, off);
            if (lane == 0) out[b * 6 + od] = p + brr[od];
        }
    }
}

extern "C" void kernel_launch(void* const* d_in, const int* in_sizes, int n_in,
                              void* d_out, int out_size)
{
    const float* x   = (const float*)d_in[0];
    const float* pos = (const float*)d_in[1];
    // d_in[2] = batch (int64), implicit in layout
    const float* W1a = (const float*)d_in[3];
    const float* b1a = (const float*)d_in[4];
    const float* W2a = (const float*)d_in[5];
    const float* b2a = (const float*)d_in[6];
    const float* W1b = (const float*)d_in[7];
    const float* b1b = (const float*)d_in[8];
    const float* W2b = (const float*)d_in[9];
    const float* b2b = (const float*)d_in[10];
    const float* W1c = (const float*)d_in[11];
    const float* b1c = (const float*)d_in[12];
    const float* W2c = (const float*)d_in[13];
    const float* b2c = (const float*)d_in[14];
    const float* Wr  = (const float*)d_in[15];
    const float* brr = (const float*)d_in[16];
    float* out = (float*)d_out;

    const size_t smem = sizeof(SmemLayout);
    cudaFuncSetAttribute(gcn_fused_kernel,
                         cudaFuncAttributeMaxDynamicSharedMemorySize, (int)smem);

    gcn_fused_kernel<<<NGRAPH, 512, smem>>>(
        x, pos,
        W1a, b1a, W2a, b2a,
        W1b, b1b, W2b, b2b,
        W1c, b1c, W2c, b2c,
        Wr, brr, out);
}